// round 15
// baseline (speedup 1.0000x reference)
#include <cuda_runtime.h>
#include <math.h>

// ---------------------------------------------------------------------------
// R15 = R13 (best) + pos-split parallel phase C for stages 1-2.
//   prep_weights <<<24,256>>> : tap-combined weights -> g_wsh (once)
//   fused_kan    <<<512,256>>>: one sample/block, 4 stages in SMEM
// Stages 1-2: phase C splits the 4 (pos) taps across lanes (l = pix*4+pos),
//   partial accs reduced with 2x shfl_xor -> 4x shorter dependency chains,
//   4x more active lanes. Stages 3-4: R13's NPX tiling + pair-packed fb.
// ---------------------------------------------------------------------------

#define F0A make_float4(0.0f, 0.125f, 0.75f, 0.125f)
#define F0B make_float2(0.0f, 0.0f)

__device__ float4 g_wsh[4 * 384];

__device__ __forceinline__ float ftanh(float x) {
    float e = __expf(2.0f * x);
    return 1.0f - __fdividef(2.0f, e + 1.0f);
}

__device__ __forceinline__ void spline_feats(float v, float4& fa, float2& fb) {
    const float H = 2.0f / 3.0f;
    float g[8];
#pragma unroll
    for (int i = 0; i < 8; i++) g[i] = (float)(i - 2) * H - 1.0f;
    float b0[7];
#pragma unroll
    for (int i = 0; i < 7; i++)
        b0[i] = (v >= g[i] && v < g[i + 1]) ? 1.0f : 0.0f;
    float b1[6];
#pragma unroll
    for (int i = 0; i < 6; i++)
        b1[i] = (v - g[i]) * (1.0f / (g[i + 1] - g[i])) * b0[i]
              + (g[i + 2] - v) * (1.0f / (g[i + 2] - g[i + 1])) * b0[i + 1];
    float b2[5];
#pragma unroll
    for (int i = 0; i < 5; i++)
        b2[i] = (v - g[i]) * (1.0f / (g[i + 2] - g[i])) * b1[i]
              + (g[i + 3] - v) * (1.0f / (g[i + 3] - g[i + 1])) * b1[i + 1];
    fa = make_float4(b2[0], b2[1], b2[2], b2[3]);
    fb = make_float2(b2[4], fmaxf(v, 0.0f));
}

template <int COUT>
__device__ __forceinline__ void fmaC(float s, float4 w, float4& a) {
    a.x = fmaf(s, w.x, a.x);
    a.y = fmaf(s, w.y, a.y);
    a.z = fmaf(s, w.z, a.z);
    if (COUT == 4) a.w = fmaf(s, w.w, a.w);
}

// ----------------------------- prep kernel ---------------------------------
__global__ void prep_weights(
    const float* __restrict__ bw1, const float* __restrict__ sw1,
    const float* __restrict__ bw2, const float* __restrict__ sw2,
    const float* __restrict__ bw3, const float* __restrict__ sw3,
    const float* __restrict__ bw4, const float* __restrict__ sw4)
{
    int idx = blockIdx.x * 256 + threadIdx.x;
    if (idx >= 4 * 1536) return;
    int s = idx / 1536, e = idx % 1536;
    const float* bw = (s == 0) ? bw1 : (s == 1) ? bw2 : (s == 2) ? bw3 : bw4;
    const float* sw = (s == 0) ? sw1 : (s == 1) ? sw2 : (s == 2) ? sw3 : sw4;
    const int COUT = (s == 3) ? 3 : 4;

    int co  = e & 3;
    int wf  = (e >> 2) % 6;
    int c   = (e / 24) & 3;
    int pos = (e / 96) & 3;
    int p   = e / 384;
    int py = p >> 1, px = p & 1;
    int ry = pos >> 1, rx = pos & 1;
    float val = 0.0f;
    if (co < COUT) {
        int ky0 = ry * (1 + py), nky = 1 + (ry ^ py);
        int kx0 = rx * (1 + px), nkx = 1 + (rx ^ px);
        for (int a = 0; a < nky; a++)
            for (int bb = 0; bb < nkx; bb++) {
                int j = c * 9 + (ky0 + a) * 3 + (kx0 + bb);
                val += (wf == 5) ? bw[co * 36 + j]
                                 : sw[(co * 36 + j) * 5 + wf];
            }
    }
    reinterpret_cast<float*>(g_wsh)[idx] = val;
}

// -------------------- small stage (pos-split phase C) ----------------------
template <int HIN, int COUT>
__device__ __forceinline__ void do_stage_par(
    const float4* __restrict__ gw,
    float* act, float4* featA, float2* featB, float4* wsh4)
{
    constexpr int S2   = HIN * HIN;
    constexpr int NSRC = 4 * S2;
    constexpr int HOUT = 2 * HIN;
    constexpr int HP   = HIN + 2;
    constexpr int S2P  = HP * HP;
    const int tid = threadIdx.x;

    // weight copy
#pragma unroll
    for (int k = 0; k < 2; k++) {
        int i = tid + k * 256;
        if (i < 384) wsh4[i] = __ldg(gw + i);
    }
    // border ring
    {
        constexpr int NB = 2 * HP + 2 * HIN;
        for (int e = tid; e < 4 * NB; e += 256) {
            int c = e / NB, r = e % NB;
            int y, x;
            if (r < 2 * HP) { y = (r < HP) ? 0 : HP - 1; x = (r < HP) ? r : r - HP; }
            else { int r2 = r - 2 * HP;
                   y = 1 + ((r2 < HIN) ? r2 : r2 - HIN);
                   x = (r2 < HIN) ? 0 : HP - 1; }
            int slot = c * S2P + y * HP + x;
            featA[slot] = F0A;
            featB[slot] = F0B;
        }
    }
    // featurize
    if (tid < NSRC) {
        int c = tid / S2, rem = tid % S2;
        int y = rem / HIN, x = rem % HIN;
        float4 fa; float2 fb;
        spline_feats(act[tid], fa, fb);
        int slot = c * S2P + (y + 1) * HP + (x + 1);
        featA[slot] = fa;
        featB[slot] = fb;
    }
    __syncthreads();

    // phase C: l = pix*4 + pos (pos in lane bits 0-1, intra-warp shuffle)
    const int p   = tid >> 6;
    const int l   = tid & 63;
    const int pos = l & 3;
    const int pix = l >> 2;
    const int py = p >> 1, px = p & 1;
    const int ry = pos >> 1, rx = pos & 1;

    float4 acc = make_float4(0.f, 0.f, 0.f, 0.f);
    int Yb = 0, X = 0;
    if (pix < S2) {
        Yb = pix / HIN; X = pix % HIN;
        const int off0 = (Yb + py + ry) * HP + X + px + rx;
        const float4* wp = wsh4 + (p * 4 + pos) * 24;
#pragma unroll
        for (int c = 0; c < 4; c++) {
            int off = off0 + c * S2P;
            float4 fa = featA[off];
            float2 fb = featB[off];
            const float4* w = wp + c * 6;
            fmaC<COUT>(fa.x, w[0], acc);
            fmaC<COUT>(fa.y, w[1], acc);
            fmaC<COUT>(fa.z, w[2], acc);
            fmaC<COUT>(fa.w, w[3], acc);
            fmaC<COUT>(fb.x, w[4], acc);
            fmaC<COUT>(fb.y, w[5], acc);
        }
    }
    // reduce partial sums over pos
#pragma unroll
    for (int m = 1; m <= 2; m <<= 1) {
        acc.x += __shfl_xor_sync(0xffffffffu, acc.x, m);
        acc.y += __shfl_xor_sync(0xffffffffu, acc.y, m);
        acc.z += __shfl_xor_sync(0xffffffffu, acc.z, m);
        acc.w += __shfl_xor_sync(0xffffffffu, acc.w, m);
    }
    if (pos == 0 && pix < S2) {
        int y = 2 * Yb + py, x = 2 * X + px;
        act[0 * HOUT * HOUT + y * HOUT + x] = acc.x;
        act[1 * HOUT * HOUT + y * HOUT + x] = acc.y;
        act[2 * HOUT * HOUT + y * HOUT + x] = acc.z;
        act[3 * HOUT * HOUT + y * HOUT + x] = acc.w;
    }
    __syncthreads();
}

// -------------------- large stage (R13 NPX tiling) -------------------------
template <int HIN, int COUT, bool FINAL, int NPX>
__device__ __forceinline__ void do_stage(
    const float4* __restrict__ gw,
    float* act, float4* featA, float4* fbP,
    float4* wsh4, float* gout)
{
    constexpr int S2    = HIN * HIN;
    constexpr int NSRC  = 4 * S2;
    constexpr int HOUT  = 2 * HIN;
    constexpr int HP    = HIN + 2;
    constexpr int S2P   = HP * HP;
    constexpr int ACT_L = S2 / NPX;
    constexpr int JSTR  = ACT_L / HIN;
    constexpr int POFF  = JSTR * NPX / 2;            // row-pair offset
    constexpr int S2FB  = (HP - POFF) * HP;
    const int tid = threadIdx.x;

    // weight copy
#pragma unroll
    for (int k = 0; k < 2; k++) {
        int i = tid + k * 256;
        if (i < 384) wsh4[i] = __ldg(gw + i);
    }
    // border ring
    {
        constexpr int NB = 2 * HP + 2 * HIN;
        for (int e = tid; e < 4 * NB; e += 256) {
            int c = e / NB, r = e % NB;
            int y, x;
            if (r < 2 * HP) { y = (r < HP) ? 0 : HP - 1; x = (r < HP) ? r : r - HP; }
            else { int r2 = r - 2 * HP;
                   y = 1 + ((r2 < HIN) ? r2 : r2 - HIN);
                   x = (r2 < HIN) ? 0 : HP - 1; }
            featA[c * S2P + y * HP + x] = F0A;
            if (y <= HP - 1 - POFF) {
                float2* q = reinterpret_cast<float2*>(&fbP[c * S2FB + y * HP + x]);
                q[0] = F0B;
            }
            if (y >= POFF) {
                float2* q = reinterpret_cast<float2*>(
                    &fbP[c * S2FB + (y - POFF) * HP + x]);
                q[1] = F0B;
            }
        }
    }
    // featurize
#pragma unroll
    for (int k = 0; k < (NSRC + 255) / 256; k++) {
        int lv = tid + k * 256;
        if (NSRC >= 256 || lv < NSRC) {
            int c = lv / S2, rem = lv % S2;
            int y = rem / HIN, x = rem % HIN;
            float4 fa; float2 fb;
            spline_feats(act[lv], fa, fb);
            int yp = y + 1, xp = x + 1;
            featA[c * S2P + yp * HP + xp] = fa;
            if (yp <= HP - 1 - POFF) {
                float2* q = reinterpret_cast<float2*>(&fbP[c * S2FB + yp * HP + xp]);
                q[0] = fb;
            }
            if (yp >= POFF) {
                float2* q = reinterpret_cast<float2*>(
                    &fbP[c * S2FB + (yp - POFF) * HP + xp]);
                q[1] = fb;
            }
        }
    }
    __syncthreads();

    // phase C
    const int p  = tid >> 6;
    const int l  = tid & 63;
    const int py = p >> 1, px = p & 1;

    if (ACT_L >= 64 || l < ACT_L) {
        const int Yb = l / HIN;
        const int X  = l % HIN;
        const int base = (Yb + py) * HP + X + px;

        float4 acc[NPX];
#pragma unroll
        for (int j = 0; j < NPX; j++) acc[j] = make_float4(0.f, 0.f, 0.f, 0.f);

#pragma unroll
        for (int pos = 0; pos < 4; pos++) {
            const int ry = pos >> 1, rx = pos & 1;
            const float4* wp = wsh4 + (p * 4 + pos) * 24;
#pragma unroll
            for (int c = 0; c < 4; c++) {
                const int off = base + c * S2P + ry * HP + rx;
                float4 fa[NPX];
                float4 fbQ[NPX / 2];
#pragma unroll
                for (int j = 0; j < NPX; j++)
                    fa[j] = featA[off + j * JSTR * HP];
                const int offb = c * S2FB + base + ry * HP + rx;
#pragma unroll
                for (int k = 0; k < NPX / 2; k++)
                    fbQ[k] = fbP[offb + k * JSTR * HP];
                const float4* w = wp + c * 6;
#pragma unroll
                for (int f = 0; f < 6; f++) {
                    float4 wv = w[f];
#pragma unroll
                    for (int j = 0; j < NPX; j++) {
                        float s;
                        if (f < 4) {
                            s = (f == 0) ? fa[j].x : (f == 1) ? fa[j].y
                              : (f == 2) ? fa[j].z : fa[j].w;
                        } else {
                            s = (j < NPX / 2)
                              ? ((f == 4) ? fbQ[j].x : fbQ[j].y)
                              : ((f == 4) ? fbQ[j - NPX / 2].z
                                          : fbQ[j - NPX / 2].w);
                        }
                        fmaC<COUT>(s, wv, acc[j]);
                    }
                }
            }
        }

        // write outputs
#pragma unroll
        for (int j = 0; j < NPX; j++) {
            int Y = Yb + j * JSTR;
            int y = 2 * Y + py, x = 2 * X + px;
            if (FINAL) {
                gout[0 * HOUT * HOUT + y * HOUT + x] = ftanh(acc[j].x);
                gout[1 * HOUT * HOUT + y * HOUT + x] = ftanh(acc[j].y);
                gout[2 * HOUT * HOUT + y * HOUT + x] = ftanh(acc[j].z);
            } else {
                act[0 * HOUT * HOUT + y * HOUT + x] = acc[j].x;
                act[1 * HOUT * HOUT + y * HOUT + x] = acc[j].y;
                act[2 * HOUT * HOUT + y * HOUT + x] = acc[j].z;
                act[3 * HOUT * HOUT + y * HOUT + x] = acc[j].w;
            }
        }
    }
    __syncthreads();
}

// ----------------------------- fused kernel --------------------------------
__global__ void __launch_bounds__(256, 4) fused_kan_kernel(
    const float* __restrict__ x,
    const float* __restrict__ lin_w,
    const float* __restrict__ lin_b,
    float* __restrict__ out)
{
    __shared__ float  act[1024];
    __shared__ float4 featA[4 * 18 * 18];
    __shared__ float2 featB[4 * 6 * 6];     // small stages only
    __shared__ float4 fbP[4 * 10 * 18];     // pair-packed fb (stages 3,4)
    __shared__ float4 wsh4[384];

    const int tid = threadIdx.x;
    const int b   = blockIdx.x;

    // linear + relu
    if (tid < 64) {
        int j = tid >> 2, qp = tid & 3;
        const float* xr = x + b * 100 + qp * 25;
        const float* wr = lin_w + j * 100 + qp * 25;
        float acc = 0.0f;
#pragma unroll
        for (int i = 0; i < 25; i++) acc = fmaf(xr[i], wr[i], acc);
        acc += __shfl_xor_sync(0xffffffffu, acc, 1);
        acc += __shfl_xor_sync(0xffffffffu, acc, 2);
        if (qp == 0) act[j] = fmaxf(acc + lin_b[j], 0.0f);
    }
    __syncthreads();

    do_stage_par<2, 4>(g_wsh,       act, featA, featB, wsh4);
    do_stage_par<4, 4>(g_wsh + 384, act, featA, featB, wsh4);
    do_stage<8, 4, false, 2>(g_wsh + 768,  act, featA, fbP, wsh4, nullptr);
    do_stage<16, 3, true, 4>(g_wsh + 1152, act, featA, fbP, wsh4,
                             out + (size_t)b * 3 * 32 * 32);
}

// ---------------------------------------------------------------------------
extern "C" void kernel_launch(void* const* d_in, const int* in_sizes, int n_in,
                              void* d_out, int out_size) {
    const float* x     = (const float*)d_in[0];
    const float* lin_w = (const float*)d_in[1];
    const float* lin_b = (const float*)d_in[2];
    const float* bw1   = (const float*)d_in[3];
    const float* sw1   = (const float*)d_in[4];
    const float* bw2   = (const float*)d_in[5];
    const float* sw2   = (const float*)d_in[6];
    const float* bw3   = (const float*)d_in[7];
    const float* sw3   = (const float*)d_in[8];
    const float* bw4   = (const float*)d_in[9];
    const float* sw4   = (const float*)d_in[10];

    prep_weights<<<24, 256>>>(bw1, sw1, bw2, sw2, bw3, sw3, bw4, sw4);
    fused_kan_kernel<<<512, 256>>>(x, lin_w, lin_b, (float*)d_out);
}

// round 16
// speedup vs baseline: 1.1896x; 1.1896x over previous
#include <cuda_runtime.h>
#include <math.h>

// ---------------------------------------------------------------------------
// R16 = R13 (best kernel, untouched math) + PDL overlap of prep_weights with
// the fused kernel's prologue.
//   prep_weights <<<24,256>>> : tap-combined weights -> g_wsh, triggers
//                               programmatic launch completion
//   fused_kan    <<<512,256>>> (PDL): linear+relu first (independent of
//                               g_wsh), then cudaGridDependencySynchronize()
//                               before the first weight copy.
// Phase C structure (R13): parity warp-uniform, NPX strided pixels/thread,
// pair-packed fb for stages 3-4, haloed feature arrays, prep'd weights.
// ---------------------------------------------------------------------------

#define F0A make_float4(0.0f, 0.125f, 0.75f, 0.125f)
#define F0B make_float2(0.0f, 0.0f)

__device__ float4 g_wsh[4 * 384];

__device__ __forceinline__ float ftanh(float x) {
    float e = __expf(2.0f * x);
    return 1.0f - __fdividef(2.0f, e + 1.0f);
}

__device__ __forceinline__ void spline_feats(float v, float4& fa, float2& fb) {
    const float H = 2.0f / 3.0f;
    float g[8];
#pragma unroll
    for (int i = 0; i < 8; i++) g[i] = (float)(i - 2) * H - 1.0f;
    float b0[7];
#pragma unroll
    for (int i = 0; i < 7; i++)
        b0[i] = (v >= g[i] && v < g[i + 1]) ? 1.0f : 0.0f;
    float b1[6];
#pragma unroll
    for (int i = 0; i < 6; i++)
        b1[i] = (v - g[i]) * (1.0f / (g[i + 1] - g[i])) * b0[i]
              + (g[i + 2] - v) * (1.0f / (g[i + 2] - g[i + 1])) * b0[i + 1];
    float b2[5];
#pragma unroll
    for (int i = 0; i < 5; i++)
        b2[i] = (v - g[i]) * (1.0f / (g[i + 2] - g[i])) * b1[i]
              + (g[i + 3] - v) * (1.0f / (g[i + 3] - g[i + 1])) * b1[i + 1];
    fa = make_float4(b2[0], b2[1], b2[2], b2[3]);
    fb = make_float2(b2[4], fmaxf(v, 0.0f));
}

template <int COUT>
__device__ __forceinline__ void fmaC(float s, float4 w, float4& a) {
    a.x = fmaf(s, w.x, a.x);
    a.y = fmaf(s, w.y, a.y);
    a.z = fmaf(s, w.z, a.z);
    if (COUT == 4) a.w = fmaf(s, w.w, a.w);
}

// ----------------------------- prep kernel ---------------------------------
__global__ void prep_weights(
    const float* __restrict__ bw1, const float* __restrict__ sw1,
    const float* __restrict__ bw2, const float* __restrict__ sw2,
    const float* __restrict__ bw3, const float* __restrict__ sw3,
    const float* __restrict__ bw4, const float* __restrict__ sw4)
{
    int idx = blockIdx.x * 256 + threadIdx.x;
    if (idx < 4 * 1536) {
        int s = idx / 1536, e = idx % 1536;
        const float* bw = (s == 0) ? bw1 : (s == 1) ? bw2 : (s == 2) ? bw3 : bw4;
        const float* sw = (s == 0) ? sw1 : (s == 1) ? sw2 : (s == 2) ? sw3 : sw4;
        const int COUT = (s == 3) ? 3 : 4;

        int co  = e & 3;
        int wf  = (e >> 2) % 6;
        int c   = (e / 24) & 3;
        int pos = (e / 96) & 3;
        int p   = e / 384;
        int py = p >> 1, px = p & 1;
        int ry = pos >> 1, rx = pos & 1;
        float val = 0.0f;
        if (co < COUT) {
            int ky0 = ry * (1 + py), nky = 1 + (ry ^ py);
            int kx0 = rx * (1 + px), nkx = 1 + (rx ^ px);
            for (int a = 0; a < nky; a++)
                for (int bb = 0; bb < nkx; bb++) {
                    int j = c * 9 + (ky0 + a) * 3 + (kx0 + bb);
                    val += (wf == 5) ? bw[co * 36 + j]
                                     : sw[(co * 36 + j) * 5 + wf];
                }
        }
        reinterpret_cast<float*>(g_wsh)[idx] = val;
    }
    // allow the dependent (fused) kernel's blocks to launch now
    cudaTriggerProgrammaticLaunchCompletion();
}

// ----------------------------- one conv stage ------------------------------
template <int HIN, int COUT, bool FINAL, int NPX>
__device__ __forceinline__ void do_stage(
    const float4* __restrict__ gw,
    float* act, float4* featA, float2* featB, float4* fbP,
    float4* wsh4, float* gout)
{
    constexpr int S2    = HIN * HIN;
    constexpr int NSRC  = 4 * S2;
    constexpr int HOUT  = 2 * HIN;
    constexpr int HP    = HIN + 2;
    constexpr int S2P   = HP * HP;
    constexpr int ACT_L = S2 / NPX;                 // active lanes per parity
    constexpr int JSTR  = (NPX > 1) ? ACT_L / HIN : 1;
    constexpr bool PAIR = (NPX >= 2);
    constexpr int POFF  = PAIR ? (JSTR * NPX / 2) : 1;  // row-pair offset
    constexpr int S2FB  = (HP - POFF) * HP;         // fbP slots per channel
    const int tid = threadIdx.x;

    // --- copy combined weights from global (coalesced, L2-hot)
#pragma unroll
    for (int k = 0; k < 2; k++) {
        int i = tid + k * 256;
        if (i < 384) wsh4[i] = __ldg(gw + i);
    }

    // --- border ring: spline(0) features (zero-padding contribution)
    {
        constexpr int NB = 2 * HP + 2 * HIN;
        for (int e = tid; e < 4 * NB; e += 256) {
            int c = e / NB, r = e % NB;
            int y, x;
            if (r < 2 * HP) { y = (r < HP) ? 0 : HP - 1; x = (r < HP) ? r : r - HP; }
            else { int r2 = r - 2 * HP;
                   y = 1 + ((r2 < HIN) ? r2 : r2 - HIN);
                   x = (r2 < HIN) ? 0 : HP - 1; }
            featA[c * S2P + y * HP + x] = F0A;
            if (PAIR) {
                if (y <= HP - 1 - POFF) {
                    float2* q = reinterpret_cast<float2*>(
                        &fbP[c * S2FB + y * HP + x]);
                    q[0] = F0B;
                }
                if (y >= POFF) {
                    float2* q = reinterpret_cast<float2*>(
                        &fbP[c * S2FB + (y - POFF) * HP + x]);
                    q[1] = F0B;
                }
            } else {
                featB[c * S2P + y * HP + x] = F0B;
            }
        }
    }

    // --- featurize interior source values
#pragma unroll
    for (int k = 0; k < (NSRC + 255) / 256; k++) {
        int lv = tid + k * 256;
        if (NSRC >= 256 || lv < NSRC) {
            int c = lv / S2, rem = lv % S2;
            int y = rem / HIN, x = rem % HIN;
            float4 fa; float2 fb;
            spline_feats(act[lv], fa, fb);
            int yp = y + 1, xp = x + 1;
            featA[c * S2P + yp * HP + xp] = fa;
            if (PAIR) {
                if (yp <= HP - 1 - POFF) {
                    float2* q = reinterpret_cast<float2*>(
                        &fbP[c * S2FB + yp * HP + xp]);
                    q[0] = fb;
                }
                if (yp >= POFF) {
                    float2* q = reinterpret_cast<float2*>(
                        &fbP[c * S2FB + (yp - POFF) * HP + xp]);
                    q[1] = fb;
                }
            } else {
                featB[c * S2P + yp * HP + xp] = fb;
            }
        }
    }
    __syncthreads();

    // --- phase C
    const int p  = tid >> 6;       // warp-uniform parity
    const int l  = tid & 63;
    const int py = p >> 1, px = p & 1;

    if (ACT_L >= 64 || l < ACT_L) {
        const int Yb = l / HIN;
        const int X  = l % HIN;
        const int base = (Yb + py) * HP + X + px;   // fa flat base (sans c)

        float4 acc[NPX];
#pragma unroll
        for (int j = 0; j < NPX; j++) acc[j] = make_float4(0.f, 0.f, 0.f, 0.f);

#pragma unroll
        for (int pos = 0; pos < 4; pos++) {
            const int ry = pos >> 1, rx = pos & 1;
            const float4* wp = wsh4 + (p * 4 + pos) * 24;
#pragma unroll
            for (int c = 0; c < 4; c++) {
                const int off = base + c * S2P + ry * HP + rx;
                float4 fa[NPX];
                float2 fbv[(NPX > 1) ? 1 : NPX];     // only non-PAIR path
                float4 fbQ[(NPX >= 2) ? NPX / 2 : 1];
#pragma unroll
                for (int j = 0; j < NPX; j++)
                    fa[j] = featA[off + j * JSTR * HP];
                if (PAIR) {
                    const int offb = c * S2FB + base + ry * HP + rx;
#pragma unroll
                    for (int k = 0; k < NPX / 2; k++)
                        fbQ[k] = fbP[offb + k * JSTR * HP];
                } else {
                    fbv[0] = featB[off];
                }
                const float4* w = wp + c * 6;
#pragma unroll
                for (int f = 0; f < 6; f++) {
                    float4 wv = w[f];
#pragma unroll
                    for (int j = 0; j < NPX; j++) {
                        float s;
                        if (f < 4) {
                            s = (f == 0) ? fa[j].x : (f == 1) ? fa[j].y
                              : (f == 2) ? fa[j].z : fa[j].w;
                        } else if (PAIR) {
                            s = (j < NPX / 2)
                              ? ((f == 4) ? fbQ[j].x : fbQ[j].y)
                              : ((f == 4) ? fbQ[j - NPX / 2].z
                                          : fbQ[j - NPX / 2].w);
                        } else {
                            s = (f == 4) ? fbv[0].x : fbv[0].y;
                        }
                        fmaC<COUT>(s, wv, acc[j]);
                    }
                }
            }
        }

        // --- write outputs
#pragma unroll
        for (int j = 0; j < NPX; j++) {
            int Y = Yb + j * JSTR;
            int y = 2 * Y + py, x = 2 * X + px;
            if (FINAL) {
                gout[0 * HOUT * HOUT + y * HOUT + x] = ftanh(acc[j].x);
                gout[1 * HOUT * HOUT + y * HOUT + x] = ftanh(acc[j].y);
                gout[2 * HOUT * HOUT + y * HOUT + x] = ftanh(acc[j].z);
            } else {
                act[0 * HOUT * HOUT + y * HOUT + x] = acc[j].x;
                act[1 * HOUT * HOUT + y * HOUT + x] = acc[j].y;
                act[2 * HOUT * HOUT + y * HOUT + x] = acc[j].z;
                act[3 * HOUT * HOUT + y * HOUT + x] = acc[j].w;
            }
        }
    }
    __syncthreads();
}

// ----------------------------- fused kernel --------------------------------
__global__ void __launch_bounds__(256, 4) fused_kan_kernel(
    const float* __restrict__ x,
    const float* __restrict__ lin_w,
    const float* __restrict__ lin_b,
    float* __restrict__ out)
{
    __shared__ float  act[1024];
    __shared__ float4 featA[4 * 18 * 18];   // stage-4 sized, reused
    __shared__ float2 featB[4 * 6 * 6];     // non-pair stages (1,2)
    __shared__ float4 fbP[4 * 10 * 18];     // pair-packed fb (stages 3,4)
    __shared__ float4 wsh4[384];

    const int tid = threadIdx.x;
    const int b   = blockIdx.x;

    // linear + relu (independent of g_wsh -> runs before the PDL dependency)
    if (tid < 64) {
        int j = tid >> 2, qp = tid & 3;
        const float* xr = x + b * 100 + qp * 25;
        const float* wr = lin_w + j * 100 + qp * 25;
        float acc = 0.0f;
#pragma unroll
        for (int i = 0; i < 25; i++) acc = fmaf(xr[i], wr[i], acc);
        acc += __shfl_xor_sync(0xffffffffu, acc, 1);
        acc += __shfl_xor_sync(0xffffffffu, acc, 2);
        if (qp == 0) act[j] = fmaxf(acc + lin_b[j], 0.0f);
    }

    // wait for prep_weights' g_wsh to be visible (PDL dependency)
    cudaGridDependencySynchronize();
    __syncthreads();

    do_stage<2, 4, false, 1>(g_wsh,        act, featA, featB, fbP, wsh4, nullptr);
    do_stage<4, 4, false, 1>(g_wsh + 384,  act, featA, featB, fbP, wsh4, nullptr);
    do_stage<8, 4, false, 2>(g_wsh + 768,  act, featA, featB, fbP, wsh4, nullptr);
    do_stage<16, 3, true, 4>(g_wsh + 1152, act, featA, featB, fbP, wsh4,
                             out + (size_t)b * 3 * 32 * 32);
}

// ---------------------------------------------------------------------------
extern "C" void kernel_launch(void* const* d_in, const int* in_sizes, int n_in,
                              void* d_out, int out_size) {
    const float* x     = (const float*)d_in[0];
    const float* lin_w = (const float*)d_in[1];
    const float* lin_b = (const float*)d_in[2];
    const float* bw1   = (const float*)d_in[3];
    const float* sw1   = (const float*)d_in[4];
    const float* bw2   = (const float*)d_in[5];
    const float* sw2   = (const float*)d_in[6];
    const float* bw3   = (const float*)d_in[7];
    const float* sw3   = (const float*)d_in[8];
    const float* bw4   = (const float*)d_in[9];
    const float* sw4   = (const float*)d_in[10];

    prep_weights<<<24, 256>>>(bw1, sw1, bw2, sw2, bw3, sw3, bw4, sw4);

    // fused kernel with programmatic dependent launch (overlaps prep tail)
    cudaLaunchConfig_t cfg = {};
    cfg.gridDim  = dim3(512, 1, 1);
    cfg.blockDim = dim3(256, 1, 1);
    cfg.dynamicSmemBytes = 0;
    cfg.stream = 0;
    cudaLaunchAttribute attrs[1];
    attrs[0].id = cudaLaunchAttributeProgrammaticStreamSerialization;
    attrs[0].val.programmaticStreamSerializationAllowed = 1;
    cfg.attrs = attrs;
    cfg.numAttrs = 1;
    cudaLaunchKernelEx(&cfg, fused_kan_kernel, x, lin_w, lin_b, (float*)d_out);
}

// round 17
// speedup vs baseline: 1.2318x; 1.0354x over previous
#include <cuda_runtime.h>
#include <math.h>

// ---------------------------------------------------------------------------
// R17 = R16 (PDL + prep kernel + stages 1-3) + stage-4 contiguous ROW-PAIR
// phase C: each lane owns output rows {2g, 2g+1, 2g+8, 2g+9}; the two rows
// of a pair share 3 source rows (ry=0/1 taps overlap), cutting fa loads
// 64->48 and fbQ loads 32->24 per thread (-25% phase-C SMEM reads). FMA and
// weight-broadcast counts unchanged. fbP packing (y, y+8) already matches.
// ---------------------------------------------------------------------------

#define F0A make_float4(0.0f, 0.125f, 0.75f, 0.125f)
#define F0B make_float2(0.0f, 0.0f)

__device__ float4 g_wsh[4 * 384];

__device__ __forceinline__ float ftanh(float x) {
    float e = __expf(2.0f * x);
    return 1.0f - __fdividef(2.0f, e + 1.0f);
}

__device__ __forceinline__ void spline_feats(float v, float4& fa, float2& fb) {
    const float H = 2.0f / 3.0f;
    float g[8];
#pragma unroll
    for (int i = 0; i < 8; i++) g[i] = (float)(i - 2) * H - 1.0f;
    float b0[7];
#pragma unroll
    for (int i = 0; i < 7; i++)
        b0[i] = (v >= g[i] && v < g[i + 1]) ? 1.0f : 0.0f;
    float b1[6];
#pragma unroll
    for (int i = 0; i < 6; i++)
        b1[i] = (v - g[i]) * (1.0f / (g[i + 1] - g[i])) * b0[i]
              + (g[i + 2] - v) * (1.0f / (g[i + 2] - g[i + 1])) * b0[i + 1];
    float b2[5];
#pragma unroll
    for (int i = 0; i < 5; i++)
        b2[i] = (v - g[i]) * (1.0f / (g[i + 2] - g[i])) * b1[i]
              + (g[i + 3] - v) * (1.0f / (g[i + 3] - g[i + 1])) * b1[i + 1];
    fa = make_float4(b2[0], b2[1], b2[2], b2[3]);
    fb = make_float2(b2[4], fmaxf(v, 0.0f));
}

template <int COUT>
__device__ __forceinline__ void fmaC(float s, float4 w, float4& a) {
    a.x = fmaf(s, w.x, a.x);
    a.y = fmaf(s, w.y, a.y);
    a.z = fmaf(s, w.z, a.z);
    if (COUT == 4) a.w = fmaf(s, w.w, a.w);
}

// ----------------------------- prep kernel ---------------------------------
__global__ void prep_weights(
    const float* __restrict__ bw1, const float* __restrict__ sw1,
    const float* __restrict__ bw2, const float* __restrict__ sw2,
    const float* __restrict__ bw3, const float* __restrict__ sw3,
    const float* __restrict__ bw4, const float* __restrict__ sw4)
{
    int idx = blockIdx.x * 256 + threadIdx.x;
    if (idx < 4 * 1536) {
        int s = idx / 1536, e = idx % 1536;
        const float* bw = (s == 0) ? bw1 : (s == 1) ? bw2 : (s == 2) ? bw3 : bw4;
        const float* sw = (s == 0) ? sw1 : (s == 1) ? sw2 : (s == 2) ? sw3 : sw4;
        const int COUT = (s == 3) ? 3 : 4;

        int co  = e & 3;
        int wf  = (e >> 2) % 6;
        int c   = (e / 24) & 3;
        int pos = (e / 96) & 3;
        int p   = e / 384;
        int py = p >> 1, px = p & 1;
        int ry = pos >> 1, rx = pos & 1;
        float val = 0.0f;
        if (co < COUT) {
            int ky0 = ry * (1 + py), nky = 1 + (ry ^ py);
            int kx0 = rx * (1 + px), nkx = 1 + (rx ^ px);
            for (int a = 0; a < nky; a++)
                for (int bb = 0; bb < nkx; bb++) {
                    int j = c * 9 + (ky0 + a) * 3 + (kx0 + bb);
                    val += (wf == 5) ? bw[co * 36 + j]
                                     : sw[(co * 36 + j) * 5 + wf];
                }
        }
        reinterpret_cast<float*>(g_wsh)[idx] = val;
    }
    cudaTriggerProgrammaticLaunchCompletion();
}

// ------------------ generic stage (stages 1-3, as R13/R16) -----------------
template <int HIN, int COUT, bool FINAL, int NPX>
__device__ __forceinline__ void do_stage(
    const float4* __restrict__ gw,
    float* act, float4* featA, float2* featB, float4* fbP,
    float4* wsh4, float* gout)
{
    constexpr int S2    = HIN * HIN;
    constexpr int NSRC  = 4 * S2;
    constexpr int HOUT  = 2 * HIN;
    constexpr int HP    = HIN + 2;
    constexpr int S2P   = HP * HP;
    constexpr int ACT_L = S2 / NPX;
    constexpr int JSTR  = (NPX > 1) ? ACT_L / HIN : 1;
    constexpr bool PAIR = (NPX >= 2);
    constexpr int POFF  = PAIR ? (JSTR * NPX / 2) : 1;
    constexpr int S2FB  = (HP - POFF) * HP;
    const int tid = threadIdx.x;

#pragma unroll
    for (int k = 0; k < 2; k++) {
        int i = tid + k * 256;
        if (i < 384) wsh4[i] = __ldg(gw + i);
    }
    {
        constexpr int NB = 2 * HP + 2 * HIN;
        for (int e = tid; e < 4 * NB; e += 256) {
            int c = e / NB, r = e % NB;
            int y, x;
            if (r < 2 * HP) { y = (r < HP) ? 0 : HP - 1; x = (r < HP) ? r : r - HP; }
            else { int r2 = r - 2 * HP;
                   y = 1 + ((r2 < HIN) ? r2 : r2 - HIN);
                   x = (r2 < HIN) ? 0 : HP - 1; }
            featA[c * S2P + y * HP + x] = F0A;
            if (PAIR) {
                if (y <= HP - 1 - POFF) {
                    float2* q = reinterpret_cast<float2*>(
                        &fbP[c * S2FB + y * HP + x]);
                    q[0] = F0B;
                }
                if (y >= POFF) {
                    float2* q = reinterpret_cast<float2*>(
                        &fbP[c * S2FB + (y - POFF) * HP + x]);
                    q[1] = F0B;
                }
            } else {
                featB[c * S2P + y * HP + x] = F0B;
            }
        }
    }
#pragma unroll
    for (int k = 0; k < (NSRC + 255) / 256; k++) {
        int lv = tid + k * 256;
        if (NSRC >= 256 || lv < NSRC) {
            int c = lv / S2, rem = lv % S2;
            int y = rem / HIN, x = rem % HIN;
            float4 fa; float2 fb;
            spline_feats(act[lv], fa, fb);
            int yp = y + 1, xp = x + 1;
            featA[c * S2P + yp * HP + xp] = fa;
            if (PAIR) {
                if (yp <= HP - 1 - POFF) {
                    float2* q = reinterpret_cast<float2*>(
                        &fbP[c * S2FB + yp * HP + xp]);
                    q[0] = fb;
                }
                if (yp >= POFF) {
                    float2* q = reinterpret_cast<float2*>(
                        &fbP[c * S2FB + (yp - POFF) * HP + xp]);
                    q[1] = fb;
                }
            } else {
                featB[c * S2P + yp * HP + xp] = fb;
            }
        }
    }
    __syncthreads();

    const int p  = tid >> 6;
    const int l  = tid & 63;
    const int py = p >> 1, px = p & 1;

    if (ACT_L >= 64 || l < ACT_L) {
        const int Yb = l / HIN;
        const int X  = l % HIN;
        const int base = (Yb + py) * HP + X + px;

        float4 acc[NPX];
#pragma unroll
        for (int j = 0; j < NPX; j++) acc[j] = make_float4(0.f, 0.f, 0.f, 0.f);

#pragma unroll
        for (int pos = 0; pos < 4; pos++) {
            const int ry = pos >> 1, rx = pos & 1;
            const float4* wp = wsh4 + (p * 4 + pos) * 24;
#pragma unroll
            for (int c = 0; c < 4; c++) {
                const int off = base + c * S2P + ry * HP + rx;
                float4 fa[NPX];
                float2 fbv[(NPX > 1) ? 1 : NPX];
                float4 fbQ[(NPX >= 2) ? NPX / 2 : 1];
#pragma unroll
                for (int j = 0; j < NPX; j++)
                    fa[j] = featA[off + j * JSTR * HP];
                if (PAIR) {
                    const int offb = c * S2FB + base + ry * HP + rx;
#pragma unroll
                    for (int k = 0; k < NPX / 2; k++)
                        fbQ[k] = fbP[offb + k * JSTR * HP];
                } else {
                    fbv[0] = featB[off];
                }
                const float4* w = wp + c * 6;
#pragma unroll
                for (int f = 0; f < 6; f++) {
                    float4 wv = w[f];
#pragma unroll
                    for (int j = 0; j < NPX; j++) {
                        float s;
                        if (f < 4) {
                            s = (f == 0) ? fa[j].x : (f == 1) ? fa[j].y
                              : (f == 2) ? fa[j].z : fa[j].w;
                        } else if (PAIR) {
                            s = (j < NPX / 2)
                              ? ((f == 4) ? fbQ[j].x : fbQ[j].y)
                              : ((f == 4) ? fbQ[j - NPX / 2].z
                                          : fbQ[j - NPX / 2].w);
                        } else {
                            s = (f == 4) ? fbv[0].x : fbv[0].y;
                        }
                        fmaC<COUT>(s, wv, acc[j]);
                    }
                }
            }
        }

#pragma unroll
        for (int j = 0; j < NPX; j++) {
            int Y = Yb + j * JSTR;
            int y = 2 * Y + py, x = 2 * X + px;
            if (FINAL) {
                gout[0 * HOUT * HOUT + y * HOUT + x] = ftanh(acc[j].x);
                gout[1 * HOUT * HOUT + y * HOUT + x] = ftanh(acc[j].y);
                gout[2 * HOUT * HOUT + y * HOUT + x] = ftanh(acc[j].z);
            } else {
                act[0 * HOUT * HOUT + y * HOUT + x] = acc[j].x;
                act[1 * HOUT * HOUT + y * HOUT + x] = acc[j].y;
                act[2 * HOUT * HOUT + y * HOUT + x] = acc[j].z;
                act[3 * HOUT * HOUT + y * HOUT + x] = acc[j].w;
            }
        }
    }
    __syncthreads();
}

// ------------------ stage 4: contiguous row-pair phase C -------------------
__device__ __forceinline__ void do_stage4(
    const float4* __restrict__ gw,
    float* act, float4* featA, float4* fbP, float4* wsh4, float* gout)
{
    constexpr int HIN  = 16;
    constexpr int S2   = 256;
    constexpr int NSRC = 1024;
    constexpr int HOUT = 32;
    constexpr int HP   = 18;
    constexpr int S2P  = HP * HP;        // 324
    constexpr int POFF = 8;              // fb pack (y, y+8)
    constexpr int S2FB = (HP - POFF) * HP;  // 180
    const int tid = threadIdx.x;

    // weight copy
#pragma unroll
    for (int k = 0; k < 2; k++) {
        int i = tid + k * 256;
        if (i < 384) wsh4[i] = __ldg(gw + i);
    }
    // border ring
    {
        constexpr int NB = 2 * HP + 2 * HIN;
        for (int e = tid; e < 4 * NB; e += 256) {
            int c = e / NB, r = e % NB;
            int y, x;
            if (r < 2 * HP) { y = (r < HP) ? 0 : HP - 1; x = (r < HP) ? r : r - HP; }
            else { int r2 = r - 2 * HP;
                   y = 1 + ((r2 < HIN) ? r2 : r2 - HIN);
                   x = (r2 < HIN) ? 0 : HP - 1; }
            featA[c * S2P + y * HP + x] = F0A;
            if (y <= HP - 1 - POFF) {
                float2* q = reinterpret_cast<float2*>(&fbP[c * S2FB + y * HP + x]);
                q[0] = F0B;
            }
            if (y >= POFF) {
                float2* q = reinterpret_cast<float2*>(
                    &fbP[c * S2FB + (y - POFF) * HP + x]);
                q[1] = F0B;
            }
        }
    }
    // featurize
#pragma unroll
    for (int k = 0; k < 4; k++) {
        int lv = tid + k * 256;
        int c = lv / S2, rem = lv % S2;
        int y = rem / HIN, x = rem % HIN;
        float4 fa; float2 fb;
        spline_feats(act[lv], fa, fb);
        int yp = y + 1, xp = x + 1;
        featA[c * S2P + yp * HP + xp] = fa;
        if (yp <= HP - 1 - POFF) {
            float2* q = reinterpret_cast<float2*>(&fbP[c * S2FB + yp * HP + xp]);
            q[0] = fb;
        }
        if (yp >= POFF) {
            float2* q = reinterpret_cast<float2*>(
                &fbP[c * S2FB + (yp - POFF) * HP + xp]);
            q[1] = fb;
        }
    }
    __syncthreads();

    // phase C: rows {2g, 2g+1, 2g+8, 2g+9} per lane
    const int p  = tid >> 6;       // warp-uniform parity
    const int l  = tid & 63;
    const int py = p >> 1, px = p & 1;
    const int X  = l & 15;
    const int g  = l >> 4;
    const int R0 = 2 * g + py;     // padded base source row (pair A)
    const int col = X + px;

    float4 acc0 = make_float4(0.f, 0.f, 0.f, 0.f);
    float4 acc1 = make_float4(0.f, 0.f, 0.f, 0.f);
    float4 acc2 = make_float4(0.f, 0.f, 0.f, 0.f);
    float4 acc3 = make_float4(0.f, 0.f, 0.f, 0.f);

#pragma unroll
    for (int rx = 0; rx < 2; rx++) {
        const float4* wA = wsh4 + (p * 4 + rx) * 24;       // ry=0 (pos=rx)
        const float4* wB = wsh4 + (p * 4 + 2 + rx) * 24;   // ry=1 (pos=2+rx)
#pragma unroll
        for (int c = 0; c < 4; c++) {
            const int offA = c * S2P + R0 * HP + col + rx;
            // 6 shared source rows for 4 outputs
            float4 fa0 = featA[offA];
            float4 fa1 = featA[offA + HP];
            float4 fa2 = featA[offA + 2 * HP];
            float4 fa3 = featA[offA + 8 * HP];
            float4 fa4 = featA[offA + 9 * HP];
            float4 fa5 = featA[offA + 10 * HP];
            const float4* w0 = wA + c * 6;
            const float4* w1 = wB + c * 6;
#pragma unroll
            for (int f = 0; f < 4; f++) {
                float4 wv0 = w0[f], wv1 = w1[f];
                float s0 = (f == 0) ? fa0.x : (f == 1) ? fa0.y : (f == 2) ? fa0.z : fa0.w;
                float s1 = (f == 0) ? fa1.x : (f == 1) ? fa1.y : (f == 2) ? fa1.z : fa1.w;
                float s2 = (f == 0) ? fa2.x : (f == 1) ? fa2.y : (f == 2) ? fa2.z : fa2.w;
                float s3 = (f == 0) ? fa3.x : (f == 1) ? fa3.y : (f == 2) ? fa3.z : fa3.w;
                float s4 = (f == 0) ? fa4.x : (f == 1) ? fa4.y : (f == 2) ? fa4.z : fa4.w;
                float s5 = (f == 0) ? fa5.x : (f == 1) ? fa5.y : (f == 2) ? fa5.z : fa5.w;
                fmaC<3>(s0, wv0, acc0); fmaC<3>(s1, wv1, acc0);
                fmaC<3>(s1, wv0, acc1); fmaC<3>(s2, wv1, acc1);
                fmaC<3>(s3, wv0, acc2); fmaC<3>(s4, wv1, acc2);
                fmaC<3>(s4, wv0, acc3); fmaC<3>(s5, wv1, acc3);
            }
            // fb: rows R0..R0+2 cover both pairs via .xy (A) / .zw (B)
            const int offB = c * S2FB + R0 * HP + col + rx;
            float4 q0 = fbP[offB];
            float4 q1 = fbP[offB + HP];
            float4 q2 = fbP[offB + 2 * HP];
            {
                float4 wv0 = w0[4], wv1 = w1[4];   // f=4 (b-spline base 4)
                fmaC<3>(q0.x, wv0, acc0); fmaC<3>(q1.x, wv1, acc0);
                fmaC<3>(q1.x, wv0, acc1); fmaC<3>(q2.x, wv1, acc1);
                fmaC<3>(q0.z, wv0, acc2); fmaC<3>(q1.z, wv1, acc2);
                fmaC<3>(q1.z, wv0, acc3); fmaC<3>(q2.z, wv1, acc3);
            }
            {
                float4 wv0 = w0[5], wv1 = w1[5];   // f=5 (relu)
                fmaC<3>(q0.y, wv0, acc0); fmaC<3>(q1.y, wv1, acc0);
                fmaC<3>(q1.y, wv0, acc1); fmaC<3>(q2.y, wv1, acc1);
                fmaC<3>(q0.w, wv0, acc2); fmaC<3>(q1.w, wv1, acc2);
                fmaC<3>(q1.w, wv0, acc3); fmaC<3>(q2.w, wv1, acc3);
            }
        }
    }

    // write outputs: Y = {2g, 2g+1, 2g+8, 2g+9}
    {
        const int x = 2 * X + px;
#pragma unroll
        for (int j = 0; j < 4; j++) {
            int Y = 2 * g + ((j & 1)) + ((j >> 1) * 8);
            int y = 2 * Y + py;
            float4 a = (j == 0) ? acc0 : (j == 1) ? acc1 : (j == 2) ? acc2 : acc3;
            gout[0 * HOUT * HOUT + y * HOUT + x] = ftanh(a.x);
            gout[1 * HOUT * HOUT + y * HOUT + x] = ftanh(a.y);
            gout[2 * HOUT * HOUT + y * HOUT + x] = ftanh(a.z);
        }
    }
    __syncthreads();
}

// ----------------------------- fused kernel --------------------------------
__global__ void __launch_bounds__(256, 4) fused_kan_kernel(
    const float* __restrict__ x,
    const float* __restrict__ lin_w,
    const float* __restrict__ lin_b,
    float* __restrict__ out)
{
    __shared__ float  act[1024];
    __shared__ float4 featA[4 * 18 * 18];
    __shared__ float2 featB[4 * 6 * 6];
    __shared__ float4 fbP[4 * 10 * 18];
    __shared__ float4 wsh4[384];

    const int tid = threadIdx.x;
    const int b   = blockIdx.x;

    // linear + relu (independent of g_wsh -> before the PDL dependency)
    if (tid < 64) {
        int j = tid >> 2, qp = tid & 3;
        const float* xr = x + b * 100 + qp * 25;
        const float* wr = lin_w + j * 100 + qp * 25;
        float acc = 0.0f;
#pragma unroll
        for (int i = 0; i < 25; i++) acc = fmaf(xr[i], wr[i], acc);
        acc += __shfl_xor_sync(0xffffffffu, acc, 1);
        acc += __shfl_xor_sync(0xffffffffu, acc, 2);
        if (qp == 0) act[j] = fmaxf(acc + lin_b[j], 0.0f);
    }

    cudaGridDependencySynchronize();
    __syncthreads();

    do_stage<2, 4, false, 1>(g_wsh,        act, featA, featB, fbP, wsh4, nullptr);
    do_stage<4, 4, false, 1>(g_wsh + 384,  act, featA, featB, fbP, wsh4, nullptr);
    do_stage<8, 4, false, 2>(g_wsh + 768,  act, featA, featB, fbP, wsh4, nullptr);
    do_stage4(g_wsh + 1152, act, featA, fbP, wsh4,
              out + (size_t)b * 3 * 32 * 32);
}

// ---------------------------------------------------------------------------
extern "C" void kernel_launch(void* const* d_in, const int* in_sizes, int n_in,
                              void* d_out, int out_size) {
    const float* x     = (const float*)d_in[0];
    const float* lin_w = (const float*)d_in[1];
    const float* lin_b = (const float*)d_in[2];
    const float* bw1   = (const float*)d_in[3];
    const float* sw1   = (const float*)d_in[4];
    const float* bw2   = (const float*)d_in[5];
    const float* sw2   = (const float*)d_in[6];
    const float* bw3   = (const float*)d_in[7];
    const float* sw3   = (const float*)d_in[8];
    const float* bw4   = (const float*)d_in[9];
    const float* sw4   = (const float*)d_in[10];

    prep_weights<<<24, 256>>>(bw1, sw1, bw2, sw2, bw3, sw3, bw4, sw4);

    cudaLaunchConfig_t cfg = {};
    cfg.gridDim  = dim3(512, 1, 1);
    cfg.blockDim = dim3(256, 1, 1);
    cfg.dynamicSmemBytes = 0;
    cfg.stream = 0;
    cudaLaunchAttribute attrs[1];
    attrs[0].id = cudaLaunchAttributeProgrammaticStreamSerialization;
    attrs[0].val.programmaticStreamSerializationAllowed = 1;
    cfg.attrs = attrs;
    cfg.numAttrs = 1;
    cudaLaunchKernelEx(&cfg, fused_kan_kernel, x, lin_w, lin_b, (float*)d_out);
}